// round 2
// baseline (speedup 1.0000x reference)
#include <cuda_runtime.h>
#include <cstdint>

// out[b, :] = (1/K) * sum_k table[idx[b,k], :]
// D = 128 floats = 32 float4 -> one warp per output row, one float4 per lane.
// Indices are int32 (JAX x64 disabled). Loaded once per warp (coalesced 128B),
// broadcast via shfl.

static constexpr int D4 = 32;  // D/4

__global__ __launch_bounds__(256) void gather_mean_k32(
    const float4* __restrict__ table,
    const int* __restrict__ idx,
    float4* __restrict__ out,
    int B)
{
    const int warp = (blockIdx.x * blockDim.x + threadIdx.x) >> 5;
    const int lane = threadIdx.x & 31;
    if (warp >= B) return;

    // one coalesced 128B load of this row's 32 indices
    int my_idx = idx[(long long)warp * 32 + lane];

    float4 acc = make_float4(0.f, 0.f, 0.f, 0.f);
#pragma unroll
    for (int k = 0; k < 32; ++k) {
        int n = __shfl_sync(0xffffffffu, my_idx, k);
        float4 v = __ldg(&table[(long long)n * D4 + lane]);
        acc.x += v.x; acc.y += v.y; acc.z += v.z; acc.w += v.w;
    }

    const float inv = 1.0f / 32.0f;
    acc.x *= inv; acc.y *= inv; acc.z *= inv; acc.w *= inv;
    out[(long long)warp * D4 + lane] = acc;
}

__global__ __launch_bounds__(256) void gather_mean_generic(
    const float4* __restrict__ table,
    const int* __restrict__ idx,
    float4* __restrict__ out,
    int B, int K)
{
    const int warp = (blockIdx.x * blockDim.x + threadIdx.x) >> 5;
    const int lane = threadIdx.x & 31;
    if (warp >= B) return;

    const int* row_idx = idx + (long long)warp * K;

    float4 acc = make_float4(0.f, 0.f, 0.f, 0.f);
    int k = 0;
    for (; k + 32 <= K; k += 32) {
        int my_idx = row_idx[k + lane];
#pragma unroll
        for (int j = 0; j < 32; ++j) {
            int n = __shfl_sync(0xffffffffu, my_idx, j);
            float4 v = __ldg(&table[(long long)n * D4 + lane]);
            acc.x += v.x; acc.y += v.y; acc.z += v.z; acc.w += v.w;
        }
    }
    for (; k < K; ++k) {
        int n = row_idx[k];
        float4 v = __ldg(&table[(long long)n * D4 + lane]);
        acc.x += v.x; acc.y += v.y; acc.z += v.z; acc.w += v.w;
    }

    const float inv = 1.0f / (float)K;
    acc.x *= inv; acc.y *= inv; acc.z *= inv; acc.w *= inv;
    out[(long long)warp * D4 + lane] = acc;
}

extern "C" void kernel_launch(void* const* d_in, const int* in_sizes, int n_in,
                              void* d_out, int out_size)
{
    const float4* table = (const float4*)d_in[0];   // [V, 128] f32
    const int*    idx   = (const int*)d_in[1];      // [B, K] int32
    float4*       out   = (float4*)d_out;           // [B, 128] f32

    const int B = out_size / 128;                   // rows of output
    const int K = (B > 0) ? (in_sizes[1] / B) : 0;

    const int threads = 256;                        // 8 warps/block, 1 row/warp
    const int blocks  = (B + 7) / 8;

    if (K == 32) {
        gather_mean_k32<<<blocks, threads>>>(table, idx, out, B);
    } else {
        gather_mean_generic<<<blocks, threads>>>(table, idx, out, B, K);
    }
}

// round 4
// speedup vs baseline: 1.0368x; 1.0368x over previous
#include <cuda_runtime.h>
#include <cstdint>

// out[b, :] = (1/K) * sum_k table[idx[b,k], :]
// D = 128 floats = 32 float4 -> one warp per output row, one float4 per lane.
// Cache policy: table gathers use createpolicy L2::evict_last (pin table in L2);
// out/idx are streaming (evict-first) so they never displace table lines.

static constexpr int D4 = 32;  // D/4

__device__ __forceinline__ float4 ldg_evict_last(const float4* p) {
    float4 v;
    asm volatile(
        "{\n\t"
        ".reg .b64 pol;\n\t"
        "createpolicy.fractional.L2::evict_last.b64 pol, 1.0;\n\t"
        "ld.global.nc.L2::cache_hint.v4.f32 {%0,%1,%2,%3}, [%4], pol;\n\t"
        "}"
        : "=f"(v.x), "=f"(v.y), "=f"(v.z), "=f"(v.w)
        : "l"(p));
    return v;
}

__global__ __launch_bounds__(256) void gather_mean_k32(
    const float4* __restrict__ table,
    const int* __restrict__ idx,
    float4* __restrict__ out,
    int B)
{
    const int warp = (blockIdx.x * blockDim.x + threadIdx.x) >> 5;
    const int lane = threadIdx.x & 31;
    if (warp >= B) return;

    // one coalesced 128B streaming load of this row's 32 indices
    int my_idx = __ldcs(&idx[(long long)warp * 32 + lane]);

    float4 acc = make_float4(0.f, 0.f, 0.f, 0.f);
#pragma unroll
    for (int k = 0; k < 32; ++k) {
        int n = __shfl_sync(0xffffffffu, my_idx, k);
        float4 v = ldg_evict_last(&table[(long long)n * D4 + lane]);
        acc.x += v.x; acc.y += v.y; acc.z += v.z; acc.w += v.w;
    }

    const float inv = 1.0f / 32.0f;
    acc.x *= inv; acc.y *= inv; acc.z *= inv; acc.w *= inv;
    __stcs(&out[(long long)warp * D4 + lane], acc);
}

__global__ __launch_bounds__(256) void gather_mean_generic(
    const float4* __restrict__ table,
    const int* __restrict__ idx,
    float4* __restrict__ out,
    int B, int K)
{
    const int warp = (blockIdx.x * blockDim.x + threadIdx.x) >> 5;
    const int lane = threadIdx.x & 31;
    if (warp >= B) return;

    const int* row_idx = idx + (long long)warp * K;

    float4 acc = make_float4(0.f, 0.f, 0.f, 0.f);
    int k = 0;
    for (; k + 32 <= K; k += 32) {
        int my_idx = __ldcs(&row_idx[k + lane]);
#pragma unroll
        for (int j = 0; j < 32; ++j) {
            int n = __shfl_sync(0xffffffffu, my_idx, j);
            float4 v = ldg_evict_last(&table[(long long)n * D4 + lane]);
            acc.x += v.x; acc.y += v.y; acc.z += v.z; acc.w += v.w;
        }
    }
    for (; k < K; ++k) {
        int n = row_idx[k];
        float4 v = ldg_evict_last(&table[(long long)n * D4 + lane]);
        acc.x += v.x; acc.y += v.y; acc.z += v.z; acc.w += v.w;
    }

    const float inv = 1.0f / (float)K;
    acc.x *= inv; acc.y *= inv; acc.z *= inv; acc.w *= inv;
    __stcs(&out[(long long)warp * D4 + lane], acc);
}

extern "C" void kernel_launch(void* const* d_in, const int* in_sizes, int n_in,
                              void* d_out, int out_size)
{
    const float4* table = (const float4*)d_in[0];   // [V, 128] f32
    const int*    idx   = (const int*)d_in[1];      // [B, K] int32
    float4*       out   = (float4*)d_out;           // [B, 128] f32

    const int B = out_size / 128;                   // rows of output
    const int K = (B > 0) ? (in_sizes[1] / B) : 0;

    const int threads = 256;                        // 8 warps/block, 1 row/warp
    const int blocks  = (B + 7) / 8;

    if (K == 32) {
        gather_mean_k32<<<blocks, threads>>>(table, idx, out, B);
    } else {
        gather_mean_generic<<<blocks, threads>>>(table, idx, out, B, K);
    }
}